// round 11
// baseline (speedup 1.0000x reference)
#include <cuda_runtime.h>

#define NN    8192      // nodes
#define SDIM  64        // input dim
#define ODIM  32        // out dim
#define EMAX  131072    // edges
#define ALPHA 0.2f

// ---------------- device scratch (no allocations allowed) ----------------
__device__ float    g_ssd[NN * 8];    // [node][0..3]=src scores, [4..7]=dst scores
__device__ float    g_nv[EMAX];       // per-edge exp(score)
__device__ float    g_csum[NN];       // per-column (dst) sum of exp
__device__ int      g_badflag;        // 1 if edges not grouped by src
__device__ unsigned g_done;           // arrival counter for fallback path

// 1) fused prep+scores. 256 blocks x 256 threads.
//    Each block recomputes the 512-entry w_eff with warp-wide dot products
//    (one 128B coalesced load per entry -> 16MB total L2 reads, cheap),
//    then computes scores for its 32 nodes (4 per warp).
__global__ void __launch_bounds__(256)
scores_kernel(const float* __restrict__ x, const float* __restrict__ W,
              const float* __restrict__ a) {
    __shared__ float sweff[8 * SDIM];     // [v*4+h][s]
    const int tid  = threadIdx.x;
    const int warp = tid >> 5;
    const int lane = tid & 31;

    // init scratch (each global index touched exactly once across the grid)
    {
        unsigned i = blockIdx.x * 256u + tid;      // 65536 threads, NN=8192
        if (i < NN) g_csum[i] = 0.0f;
        if (i == 0) { g_badflag = 0; g_done = 0u; }
    }

    // w_eff[k] for k=(v*4+h)*64+s : dot(W[h][s][:], a[h][v*O:])  (ODIM==32==warp)
    for (int k = warp; k < 8 * SDIM; k += 8) {
        int v = k >> 8;
        int h = (k >> 6) & 3;
        int s = k & 63;
        float p = W[h * (SDIM * ODIM) + s * ODIM + lane] *
                  a[h * (2 * ODIM) + v * ODIM + lane];
        #pragma unroll
        for (int off = 16; off > 0; off >>= 1)
            p += __shfl_down_sync(0xffffffffu, p, off);
        if (lane == 0) sweff[k] = p;
    }
    __syncthreads();

    // scores: 4 nodes per warp, unrolled for MLP
    const int node0 = blockIdx.x * 32 + warp * 4;
    #pragma unroll
    for (int j = 0; j < 4; j++) {
        int node = node0 + j;
        float x0 = x[node * SDIM + lane];
        float x1 = x[node * SDIM + 32 + lane];
        float acc[8];
        #pragma unroll
        for (int i = 0; i < 8; i++)
            acc[i] = x0 * sweff[i * SDIM + lane] + x1 * sweff[i * SDIM + 32 + lane];
        #pragma unroll
        for (int off = 16; off > 0; off >>= 1) {
            #pragma unroll
            for (int i = 0; i < 8; i++)
                acc[i] += __shfl_down_sync(0xffffffffu, acc[i], off);
        }
        if (lane < 8)   // lane i holds acc[i] head value? no: acc[i] reduced into lane0
            ;
        if (lane == 0) {
            float4* ss4 = (float4*)(g_ssd + node * 8);
            ss4[0] = make_float4(acc[0], acc[1], acc[2], acc[3]);
            ss4[1] = make_float4(acc[4], acc[5], acc[6], acc[7]);
        }
    }
}

// 2) per-edge score, exp (scores bounded << 88: no max shift), column sum.
//    2 edges per thread, vectorized index/value loads. Also validates the
//    "edges grouped by src" layout used by the fused fill/scatter.
__global__ void __launch_bounds__(256)
edge_kernel(const int* __restrict__ edges, const float* __restrict__ values,
            const float* __restrict__ wlin, const float* __restrict__ blin,
            int E, int deg) {
    int t  = blockIdx.x * 256 + threadIdx.x;
    int e0 = t * 2;
    if (e0 >= E) return;
    int2   s2 = *(const int2*)(edges + e0);
    int2   d2 = *(const int2*)(edges + E + e0);
    float2 v2 = *(const float2*)(values + e0);
    if (s2.x != e0 / deg || s2.y != (e0 + 1) / deg) g_badflag = 1;

    float w0 = wlin[0], w1 = wlin[1], w2 = wlin[2], w3 = wlin[3], b0 = blin[0];
    float ex[2];
    int   srcs[2] = { s2.x, s2.y };
    int   dsts[2] = { d2.x, d2.y };
    float vals[2] = { v2.x, v2.y };
    #pragma unroll
    for (int j = 0; j < 2; j++) {
        const float4* sp = (const float4*)(g_ssd + srcs[j] * 8);
        const float4* dp = (const float4*)(g_ssd + dsts[j] * 8);
        float4 ss = sp[0];
        float4 sd = dp[1];
        float t0 = ss.x + sd.x; t0 = t0 > 0.f ? t0 : ALPHA * t0;
        float t1 = ss.y + sd.y; t1 = t1 > 0.f ? t1 : ALPHA * t1;
        float t2 = ss.z + sd.z; t2 = t2 > 0.f ? t2 : ALPHA * t2;
        float t3 = ss.w + sd.w; t3 = t3 > 0.f ? t3 : ALPHA * t3;
        float mt = b0 + w0 * t0 + w1 * t1 + w2 * t2 + w3 * t3;
        ex[j] = expf(vals[j] * mt);
    }
    *(float2*)(g_nv + e0) = make_float2(ex[0], ex[1]);
    atomicAdd(&g_csum[dsts[0]], ex[0]);
    atomicAdd(&g_csum[dsts[1]], ex[1]);
}

// 3) fused fill + scatter. 2 blocks per row (half-row each = 1024 float4),
//    plain float4 stores (best-measured config). Each half-block inline-
//    scatters the row's edges whose dst falls in its half. If the grouping
//    assumption failed, the LAST block performs a full general scatter.
__global__ void __launch_bounds__(256)
fill_scatter_kernel(float* __restrict__ out, const int* __restrict__ edges,
                    int E, int deg) {
    const int b    = blockIdx.x;       // 0..16383
    const int r    = b >> 1;           // row = src node
    const int half = b & 1;
    float4* row4 = (float4*)(out + (long)r * NN) + half * (NN / 8);
    float4 z = make_float4(0.f, 0.f, 0.f, 0.f);
    #pragma unroll
    for (int i = 0; i < (NN / 8) / 256; i++)
        row4[threadIdx.x + i * 256] = z;
    __syncthreads();   // order zero-stores before scatter writes in this block

    if (g_badflag == 0) {
        const int lo = half * (NN / 2), hi = lo + (NN / 2);
        for (int j = threadIdx.x; j < deg; j += 256) {
            int e = r * deg + j;
            if (e < E) {
                int dst = edges[E + e];
                if (dst >= lo && dst < hi)
                    out[(long)r * NN + dst] = g_nv[e] / g_csum[dst];
            }
        }
    } else {
        // fallback: last arriving block does the general scatter
        __shared__ int lastblk;
        if (threadIdx.x == 0) {
            __threadfence();
            lastblk = (atomicAdd(&g_done, 1u) == (unsigned)(gridDim.x - 1));
        }
        __syncthreads();
        if (lastblk) {
            for (int e = threadIdx.x; e < E; e += 256) {
                int src = edges[e];
                int dst = edges[E + e];
                out[(long)src * NN + dst] = g_nv[e] / g_csum[dst];
            }
        }
    }
}

extern "C" void kernel_launch(void* const* d_in, const int* in_sizes, int n_in,
                              void* d_out, int out_size) {
    const float* x      = (const float*)d_in[0];
    const int*   edges  = (const int*)d_in[1];
    const float* values = (const float*)d_in[2];
    const float* W      = (const float*)d_in[3];
    const float* a      = (const float*)d_in[4];
    const float* wlin   = (const float*)d_in[5];
    const float* blin   = (const float*)d_in[6];
    float* out = (float*)d_out;

    int E   = in_sizes[1] / 2;        // edges is [2, E]
    int deg = E / NN;                 // 16 for this problem
    (void)n_in; (void)out_size;

    scores_kernel<<<256, 256>>>(x, W, a);
    edge_kernel<<<(E / 2 + 255) / 256, 256>>>(edges, values, wlin, blin, E, deg);
    fill_scatter_kernel<<<NN * 2, 256>>>(out, edges, E, deg);
}